// round 8
// baseline (speedup 1.0000x reference)
#include <cuda_runtime.h>
#include <cuda_bf16.h>
#include <cmath>

// SimpleHashEncoder1D: out[p, l*2 + f] = hash_table[floor((x[p]+1)/2 * scale_l + 0.5) % T, f]
//
// Numerics (LOCKED, rel_err=0.0 since R2 — do not change):
//   b = f32 1 ulp below 2.0f; scale_l = f32(16 * f32(b^l)) - 1.0f via double pow;
//   x_scaled = xn*scale + 0.5 with SEPARATE roundings (no FMA).
//
// R8: the unsorted kernel is at the l1tex wavefront floor (~78us, random per-lane
// gathers -> ~1 line per lane at high levels). Counting-sort points by x into 4096
// buckets first: warps then process near-identical x -> all 16 levels' gathers
// collapse to 1-2 lines per LDG and become L1 hits. Output rows (128B each) are
// scattered back by original index; a full-row scatter costs the same 4
// wavefronts/warp as a coalesced store, so the sort is almost pure gain.
// Atomic sort order is nondeterministic but out values are order-independent.

#define T_SIZE   524288      // 2^19
#define N_POINTS (1 << 21)   // 2097152
#define NUM_L    16
#define NB       4096        // sort buckets (~512 points each)
#define PTS_PER_THREAD 4
#define P_SLICE (N_POINTS / PTS_PER_THREAD)   // 524288

struct Scales { float s[NUM_L]; };

// Static device scratch (allocation-free rule: __device__ globals are allowed)
__device__ int2 g_srec[N_POINTS];   // sorted (x_bits, orig_idx), 16MB
__device__ int  g_hist[NB];
__device__ int  g_offs[NB];

__device__ __forceinline__ int bucket_of(float xv) {
    // any consistent monotone bucketing works; does not affect numerics
    float xn = __fmul_rn(__fadd_rn(xv, 1.0f), 0.5f);   // [0,1)
    int b = (int)(xn * (float)NB);
    return min(max(b, 0), NB - 1);
}

__global__ void k_zero() {
    int i = blockIdx.x * blockDim.x + threadIdx.x;
    if (i < NB) g_hist[i] = 0;
}

__global__ __launch_bounds__(256)
void k_hist(const float* __restrict__ x) {
    __shared__ int h[NB];
    for (int i = threadIdx.x; i < NB; i += blockDim.x) h[i] = 0;
    __syncthreads();
    int stride = gridDim.x * blockDim.x;
    for (int p = blockIdx.x * blockDim.x + threadIdx.x; p < N_POINTS; p += stride)
        atomicAdd(&h[bucket_of(x[p])], 1);
    __syncthreads();
    for (int i = threadIdx.x; i < NB; i += blockDim.x) {
        int v = h[i];
        if (v) atomicAdd(&g_hist[i], v);
    }
}

__global__ __launch_bounds__(1024)
void k_scan() {   // single block, exclusive scan of g_hist[NB] -> g_offs
    __shared__ int ps[1024];
    int t = threadIdx.x;
    int a0 = g_hist[4*t], a1 = g_hist[4*t+1], a2 = g_hist[4*t+2], a3 = g_hist[4*t+3];
    int sum = a0 + a1 + a2 + a3;
    ps[t] = sum;
    __syncthreads();
    for (int off = 1; off < 1024; off <<= 1) {
        int v = (t >= off) ? ps[t - off] : 0;
        __syncthreads();
        ps[t] += v;
        __syncthreads();
    }
    int excl = ps[t] - sum;
    g_offs[4*t]     = excl;
    g_offs[4*t + 1] = excl + a0;
    g_offs[4*t + 2] = excl + a0 + a1;
    g_offs[4*t + 3] = excl + a0 + a1 + a2;
}

__global__ __launch_bounds__(256)
void k_scatter(const float* __restrict__ x) {
    int stride = gridDim.x * blockDim.x;
    for (int p = blockIdx.x * blockDim.x + threadIdx.x; p < N_POINTS; p += stride) {
        float xv = x[p];
        int b = bucket_of(xv);
        int pos = atomicAdd(&g_offs[b], 1);
        g_srec[pos] = make_int2(__float_as_int(xv), p);
    }
}

__global__ __launch_bounds__(256)
void k_main(const float2* __restrict__ table,
            float4* __restrict__ out,
            const Scales sc)
{
    int gid = blockIdx.x * blockDim.x + threadIdx.x;   // 4M threads
    int j  = gid & 7;          // level-pair index (levels 2j, 2j+1)
    int q0 = gid >> 3;         // base SORTED position in [0, 512K)

    int l0 = j << 1;
    float s0 = sc.s[l0];
    float s1 = sc.s[l0 + 1];

    // 4 batched sorted records (lanes 0-7 broadcast each record)
    int2 rec[PTS_PER_THREAD];
#pragma unroll
    for (int k = 0; k < PTS_PER_THREAD; k++)
        rec[k] = __ldg(&g_srec[q0 + k * P_SLICE]);

    // LOCKED numerics: xn=(x+1)*0.5; v=xn*s+0.5, separate roundings, trunc==floor
    int i0[PTS_PER_THREAD], i1[PTS_PER_THREAD];
#pragma unroll
    for (int k = 0; k < PTS_PER_THREAD; k++) {
        float xn = __fmul_rn(__fadd_rn(__int_as_float(rec[k].x), 1.0f), 0.5f);
        float v0 = __fadd_rn(__fmul_rn(xn, s0), 0.5f);
        float v1 = __fadd_rn(__fmul_rn(xn, s1), 0.5f);
        i0[k] = ((int)v0) & (T_SIZE - 1);
        i1[k] = ((int)v1) & (T_SIZE - 1);
    }

    // Gathers: warp covers 4 consecutive sorted points -> near-identical indices
    // at every level -> 1-2 lines per LDG, mostly L1 hits.
    float2 f0[PTS_PER_THREAD], f1[PTS_PER_THREAD];
#pragma unroll
    for (int k = 0; k < PTS_PER_THREAD; k++) {
        f0[k] = __ldg(&table[i0[k]]);
        f1[k] = __ldg(&table[i1[k]]);
    }

    // Row-scatter store: lanes 0-7 write one full 128B row of out[orig]
    // -> 4 distinct lines per warp-store, same cost as coalesced.
#pragma unroll
    for (int k = 0; k < PTS_PER_THREAD; k++) {
        int oi = (rec[k].y << 3) + j;
        out[oi] = make_float4(f0[k].x, f0[k].y, f1[k].x, f1[k].y);
    }
}

extern "C" void kernel_launch(void* const* d_in, const int* in_sizes, int n_in,
                              void* d_out, int out_size)
{
    const float*  x     = (const float*)d_in[0];
    const float2* table = (const float2*)d_in[1];
    // d_in[2] is `bound` (== 1): folded into the normalize.
    float4* out = (float4*)d_out;

    // b = f32 value 1 ulp below 2.0f (0x3FFFFFFF)
    const float b = 1.99999988079071044921875f;
    Scales sc;
    for (int l = 0; l < NUM_L; l++) {
        double pd = pow((double)b, (double)l);   // correctly rounded double
        float  pf = (float)pd;                   // == f32 pow result
        float  q  = 16.0f * pf;                  // exact
        sc.s[l]   = q - 1.0f;                    // f32 rounding
    }

    k_zero<<<NB / 256, 256>>>();
    k_hist<<<2048, 256>>>(x);
    k_scan<<<1, 1024>>>();
    k_scatter<<<2048, 256>>>(x);

    int total_threads = (N_POINTS / PTS_PER_THREAD) * (NUM_L / 2);  // 4M
    k_main<<<total_threads / 256, 256>>>(table, out, sc);
}

// round 9
// speedup vs baseline: 1.7273x; 1.7273x over previous
#include <cuda_runtime.h>
#include <cuda_bf16.h>
#include <cmath>

// SimpleHashEncoder1D: out[p, l*2 + f] = hash_table[floor((x[p]+1)/2 * scale_l + 0.5) % T, f]
//
// Numerics (LOCKED, rel_err=0.0 since R2 — do not change):
//   b = f32 1 ulp below 2.0f; scale_l = f32(16 * f32(b^l)) - 1.0f via double pow;
//   x_scaled = xn*scale + 0.5 with SEPARATE roundings (no FMA).
//
// R9: keep the R8 bucket-sort idea, fix the sort cost.
//   - 64 segments x 32768 points; segment base in sorted array is STATIC (seg*32768)
//     -> no global scan, just 64 independent per-segment 4096-bucket scans.
//   - hist: 256 CTAs, smem counting, ~0.9M fire-and-forget global adds (was 8.4M).
//   - scatter: CTA-aggregated reservation — smem ranks (cheap spread ATOMS) + one
//     batched global atomicAdd per nonzero (seg,bucket) (~3.5K/CTA, independent)
//     (was 2M contended returning ATOMGs = 64us).
//   - main kernel unchanged from R8: sorted warps -> gathers collapse to few lines,
//     full-128B-row scatter stores by orig index (same wf cost as coalesced).
// Sort order within (cta,bucket) is nondeterministic but output values are
// order-independent -> deterministic out.

#define T_SIZE   524288      // 2^19
#define N_POINTS (1 << 21)   // 2097152
#define NUM_L    16
#define NB       4096        // buckets per segment (x-prefix)
#define NSEG     64
#define SEG_PTS  32768       // N_POINTS / NSEG
#define NKEY     (NSEG * NB) // 262144
#define PTS_PER_THREAD 4
#define P_SLICE (N_POINTS / PTS_PER_THREAD)   // 524288

struct Scales { float s[NUM_L]; };

// Static device scratch (allocation-free rule: __device__ globals allowed)
__device__ int2 g_srec[N_POINTS];   // sorted (x_bits, orig_idx), 16MB
__device__ int  g_keyhist[NKEY];    // per (seg,bucket) counts
__device__ int  g_offs[NKEY];       // running allocation cursors

__device__ __forceinline__ int bucket_of(float xv) {
    // monotone bucketing; independent of the locked index numerics
    float xn = __fmul_rn(__fadd_rn(xv, 1.0f), 0.5f);   // [0,1]
    int b = (int)(xn * (float)NB);
    return min(max(b, 0), NB - 1);
}

__global__ __launch_bounds__(1024) void k_zero() {
    g_keyhist[blockIdx.x * 1024 + threadIdx.x] = 0;    // grid = NKEY/1024
}

// 256 CTAs x 1024 thr x 8 pts; each CTA covers 8192 contiguous points = 1/4 segment
__global__ __launch_bounds__(1024) void k_hist(const float* __restrict__ x) {
    __shared__ int h[NB];
    for (int i = threadIdx.x; i < NB; i += 1024) h[i] = 0;
    __syncthreads();
    int base = blockIdx.x * 8192;
#pragma unroll
    for (int k = 0; k < 8; k++) {
        float xv = __ldg(&x[base + k * 1024 + threadIdx.x]);
        atomicAdd(&h[bucket_of(xv)], 1);
    }
    __syncthreads();
    int seg = blockIdx.x >> 2;
    for (int i = threadIdx.x; i < NB; i += 1024) {
        int v = h[i];
        if (v) atomicAdd(&g_keyhist[seg * NB + i], v);   // fire-and-forget REDG
    }
}

// 64 CTAs, one per segment: exclusive scan of 4096 counts; base = seg*SEG_PTS
__global__ __launch_bounds__(1024) void k_scan() {
    __shared__ int ps[1024];
    int seg = blockIdx.x, t = threadIdx.x;
    const int* hh = g_keyhist + seg * NB;
    int a0 = hh[4*t], a1 = hh[4*t+1], a2 = hh[4*t+2], a3 = hh[4*t+3];
    int sum = a0 + a1 + a2 + a3;
    ps[t] = sum;
    __syncthreads();
    for (int off = 1; off < 1024; off <<= 1) {
        int v = (t >= off) ? ps[t - off] : 0;
        __syncthreads();
        ps[t] += v;
        __syncthreads();
    }
    int excl = ps[t] - sum + seg * SEG_PTS;
    int* oo = g_offs + seg * NB;
    oo[4*t]     = excl;
    oo[4*t + 1] = excl + a0;
    oo[4*t + 2] = excl + a0 + a1;
    oo[4*t + 3] = excl + a0 + a1 + a2;
}

// 256 CTAs x 1024 thr x 8 pts: smem ranks + aggregated global reservation
__global__ __launch_bounds__(1024) void k_scatter(const float* __restrict__ x) {
    __shared__ int scnt[NB];    // 16KB
    __shared__ int sbase[NB];   // 16KB
    for (int i = threadIdx.x; i < NB; i += 1024) scnt[i] = 0;
    __syncthreads();
    int base = blockIdx.x * 8192;
    int seg  = blockIdx.x >> 2;

    float xv[8]; int bk[8], rk[8];
#pragma unroll
    for (int k = 0; k < 8; k++) {
        xv[k] = __ldg(&x[base + k * 1024 + threadIdx.x]);
        bk[k] = bucket_of(xv[k]);
        rk[k] = atomicAdd(&scnt[bk[k]], 1);   // cheap spread smem atomic
    }
    __syncthreads();
    // one batched independent global atomicAdd per nonzero bucket (~3.5K/CTA)
    for (int i = threadIdx.x; i < NB; i += 1024) {
        int c = scnt[i];
        if (c) sbase[i] = atomicAdd(&g_offs[seg * NB + i], c);
    }
    __syncthreads();
#pragma unroll
    for (int k = 0; k < 8; k++) {
        int pos = sbase[bk[k]] + rk[k];
        g_srec[pos] = make_int2(__float_as_int(xv[k]), base + k * 1024 + threadIdx.x);
    }
}

__global__ __launch_bounds__(256)
void k_main(const float2* __restrict__ table,
            float4* __restrict__ out,
            const Scales sc)
{
    int gid = blockIdx.x * blockDim.x + threadIdx.x;   // 4M threads
    int j  = gid & 7;          // level-pair index (levels 2j, 2j+1)
    int q0 = gid >> 3;         // base SORTED position in [0, 512K)

    int l0 = j << 1;
    float s0 = sc.s[l0];
    float s1 = sc.s[l0 + 1];

    int2 rec[PTS_PER_THREAD];
#pragma unroll
    for (int k = 0; k < PTS_PER_THREAD; k++)
        rec[k] = __ldg(&g_srec[q0 + k * P_SLICE]);

    // LOCKED numerics
    int i0[PTS_PER_THREAD], i1[PTS_PER_THREAD];
#pragma unroll
    for (int k = 0; k < PTS_PER_THREAD; k++) {
        float xn = __fmul_rn(__fadd_rn(__int_as_float(rec[k].x), 1.0f), 0.5f);
        float v0 = __fadd_rn(__fmul_rn(xn, s0), 0.5f);
        float v1 = __fadd_rn(__fmul_rn(xn, s1), 0.5f);
        i0[k] = ((int)v0) & (T_SIZE - 1);
        i1[k] = ((int)v1) & (T_SIZE - 1);
    }

    // Sorted positions -> per-LDG indices span ~1 bucket per level -> few lines
    float2 f0[PTS_PER_THREAD], f1[PTS_PER_THREAD];
#pragma unroll
    for (int k = 0; k < PTS_PER_THREAD; k++) {
        f0[k] = __ldg(&table[i0[k]]);
        f1[k] = __ldg(&table[i1[k]]);
    }

    // Full-row scatter store by original index (4 x 128B rows per warp)
#pragma unroll
    for (int k = 0; k < PTS_PER_THREAD; k++) {
        int oi = (rec[k].y << 3) + j;
        out[oi] = make_float4(f0[k].x, f0[k].y, f1[k].x, f1[k].y);
    }
}

extern "C" void kernel_launch(void* const* d_in, const int* in_sizes, int n_in,
                              void* d_out, int out_size)
{
    const float*  x     = (const float*)d_in[0];
    const float2* table = (const float2*)d_in[1];
    // d_in[2] is `bound` (== 1): folded into the normalize.
    float4* out = (float4*)d_out;

    // b = f32 value 1 ulp below 2.0f (0x3FFFFFFF)
    const float b = 1.99999988079071044921875f;
    Scales sc;
    for (int l = 0; l < NUM_L; l++) {
        double pd = pow((double)b, (double)l);   // correctly rounded double
        float  pf = (float)pd;                   // == f32 pow result
        float  q  = 16.0f * pf;                  // exact
        sc.s[l]   = q - 1.0f;                    // f32 rounding
    }

    k_zero<<<NKEY / 1024, 1024>>>();
    k_hist<<<N_POINTS / 8192, 1024>>>(x);
    k_scan<<<NSEG, 1024>>>();
    k_scatter<<<N_POINTS / 8192, 1024>>>(x);

    int total_threads = (N_POINTS / PTS_PER_THREAD) * (NUM_L / 2);  // 4M
    k_main<<<total_threads / 256, 256>>>(table, out, sc);
}

// round 10
// speedup vs baseline: 1.7581x; 1.0178x over previous
#include <cuda_runtime.h>
#include <cuda_bf16.h>
#include <cmath>

// SimpleHashEncoder1D: out[p, l*2 + f] = hash_table[floor((x[p]+1)/2 * scale_l + 0.5) % T, f]
//
// Numerics (LOCKED, rel_err=0.0 since R2 — do not change):
//   b = f32 1 ulp below 2.0f; scale_l = f32(16 * f32(b^l)) - 1.0f via double pow;
//   x_scaled = xn*scale + 0.5 with SEPARATE roundings (no FMA).
//
// R10: R9 proved the sorted main kernel is ~45us (vs 78.9 unsorted) but spent ~43us
// on a 4-kernel sort. Fuse the whole sort into ONE kernel: segment == CTA (512 CTAs
// x 4096 contiguous points), so bucket bases are CTA-local — smem histogram, smem
// block scan, direct scatter to g_srec[ctaBase + localOff]. No global hist, no
// global scan, no zero pass; x read once into registers.
// Sort order within a bucket is nondeterministic but output values are
// order-independent -> deterministic out.

#define T_SIZE   524288      // 2^19
#define N_POINTS (1 << 21)   // 2097152
#define NUM_L    16
#define NB       4096        // x-buckets per segment (width 2^-12 of x-range)
#define SORT_CTAS 512
#define SORT_THR  512
#define SEG_PTS   4096       // N_POINTS / SORT_CTAS
#define PPT_SORT  8          // SEG_PTS / SORT_THR
#define PTS_PER_THREAD 4
#define P_SLICE (N_POINTS / PTS_PER_THREAD)   // 524288

struct Scales { float s[NUM_L]; };

// Static device scratch (allocation-free rule: __device__ globals allowed)
__device__ int2 g_srec[N_POINTS];   // sorted (x_bits, orig_idx), 16MB

__device__ __forceinline__ int bucket_of(float xv) {
    // monotone bucketing; independent of the locked index numerics
    float xn = __fmul_rn(__fadd_rn(xv, 1.0f), 0.5f);   // [0,1]
    int b = (int)(xn * (float)NB);
    return min(max(b, 0), NB - 1);
}

// One CTA = one segment of 4096 contiguous points: hist -> scan -> scatter, all smem.
__global__ __launch_bounds__(SORT_THR)
void k_sort(const float* __restrict__ x)
{
    __shared__ int cnt[NB];        // counts, then allocation cursors (16KB)
    __shared__ int ps[SORT_THR];   // scan temp (2KB)

    int t = threadIdx.x;
    int base = blockIdx.x * SEG_PTS;

    for (int i = t; i < NB; i += SORT_THR) cnt[i] = 0;
    __syncthreads();

    // Pass A: load 8 points (coalesced), histogram via spread smem atomics
    float xv[PPT_SORT]; int bk[PPT_SORT];
#pragma unroll
    for (int k = 0; k < PPT_SORT; k++) {
        xv[k] = __ldg(&x[base + k * SORT_THR + t]);
        bk[k] = bucket_of(xv[k]);
        atomicAdd(&cnt[bk[k]], 1);
    }
    __syncthreads();

    // Block exclusive scan of 4096 counts (8 per thread), in place
    int a[8];
    int sum = 0;
#pragma unroll
    for (int e = 0; e < 8; e++) { a[e] = cnt[8 * t + e]; sum += a[e]; }
    ps[t] = sum;
    __syncthreads();
    for (int off = 1; off < SORT_THR; off <<= 1) {
        int v = (t >= off) ? ps[t - off] : 0;
        __syncthreads();
        ps[t] += v;
        __syncthreads();
    }
    int run = ps[t] - sum + base;   // global position of first elem of bucket 8t
#pragma unroll
    for (int e = 0; e < 8; e++) { cnt[8 * t + e] = run; run += a[e]; }
    __syncthreads();

    // Pass B: rank via cursor atomics, scatter records
#pragma unroll
    for (int k = 0; k < PPT_SORT; k++) {
        int pos = atomicAdd(&cnt[bk[k]], 1);
        g_srec[pos] = make_int2(__float_as_int(xv[k]), base + k * SORT_THR + t);
    }
}

__global__ __launch_bounds__(256)
void k_main(const float2* __restrict__ table,
            float4* __restrict__ out,
            const Scales sc)
{
    int gid = blockIdx.x * blockDim.x + threadIdx.x;   // 4M threads
    int j  = gid & 7;          // level-pair index (levels 2j, 2j+1)
    int q0 = gid >> 3;         // base SORTED position in [0, 512K)

    int l0 = j << 1;
    float s0 = sc.s[l0];
    float s1 = sc.s[l0 + 1];

    int2 rec[PTS_PER_THREAD];
#pragma unroll
    for (int k = 0; k < PTS_PER_THREAD; k++)
        rec[k] = __ldg(&g_srec[q0 + k * P_SLICE]);

    // LOCKED numerics
    int i0[PTS_PER_THREAD], i1[PTS_PER_THREAD];
#pragma unroll
    for (int k = 0; k < PTS_PER_THREAD; k++) {
        float xn = __fmul_rn(__fadd_rn(__int_as_float(rec[k].x), 1.0f), 0.5f);
        float v0 = __fadd_rn(__fmul_rn(xn, s0), 0.5f);
        float v1 = __fadd_rn(__fmul_rn(xn, s1), 0.5f);
        i0[k] = ((int)v0) & (T_SIZE - 1);
        i1[k] = ((int)v1) & (T_SIZE - 1);
    }

    // Sorted positions -> per-LDG indices span ~1 bucket per level -> few lines, L1 hits
    float2 f0[PTS_PER_THREAD], f1[PTS_PER_THREAD];
#pragma unroll
    for (int k = 0; k < PTS_PER_THREAD; k++) {
        f0[k] = __ldg(&table[i0[k]]);
        f1[k] = __ldg(&table[i1[k]]);
    }

    // Full-row scatter store by original index (lanes 0-7 = one 128B row)
#pragma unroll
    for (int k = 0; k < PTS_PER_THREAD; k++) {
        int oi = (rec[k].y << 3) + j;
        out[oi] = make_float4(f0[k].x, f0[k].y, f1[k].x, f1[k].y);
    }
}

extern "C" void kernel_launch(void* const* d_in, const int* in_sizes, int n_in,
                              void* d_out, int out_size)
{
    const float*  x     = (const float*)d_in[0];
    const float2* table = (const float2*)d_in[1];
    // d_in[2] is `bound` (== 1): folded into the normalize.
    float4* out = (float4*)d_out;

    // b = f32 value 1 ulp below 2.0f (0x3FFFFFFF)
    const float b = 1.99999988079071044921875f;
    Scales sc;
    for (int l = 0; l < NUM_L; l++) {
        double pd = pow((double)b, (double)l);   // correctly rounded double
        float  pf = (float)pd;                   // == f32 pow result
        float  q  = 16.0f * pf;                  // exact
        sc.s[l]   = q - 1.0f;                    // f32 rounding
    }

    k_sort<<<SORT_CTAS, SORT_THR>>>(x);

    int total_threads = (N_POINTS / PTS_PER_THREAD) * (NUM_L / 2);  // 4M
    k_main<<<total_threads / 256, 256>>>(table, out, sc);
}